// round 14
// baseline (speedup 1.0000x reference)
#include <cuda_runtime.h>

#define NSEQ  16384
#define DIMX  512
#define NH    8
#define DH    64
#define INNER 512
#define ML    256
#define LP    64
#define KSZ   33
#define TIN   1536

// ---------------- scratch (device globals; no allocations allowed) ----------
__device__ float g_h[NSEQ * DIMX];
__device__ float g_qkv[NSEQ * TIN];
__device__ float g_ql[NH * ML * DH];
__device__ float g_kl[NH * ML * DH];
__device__ float g_a2[NH * ML * ML];
__device__ float g_zb1[NH * ML * ML];
__device__ float g_zb2[NH * ML * ML];
__device__ float g_az[NH * ML * ML];
__device__ float g_w2[NH * ML * ML];
__device__ float g_w4[NH * ML * ML];
__device__ float g_attn3[NH * ML * NSEQ];   // 134 MB
__device__ float g_t1[NH * ML * DH];
__device__ float g_t2[NH * ML * DH];
__device__ float g_attnout[NSEQ * INNER];
__device__ float g_colmax;
__device__ float g_rowmax;

__device__ __forceinline__ float* pickbuf(int s) {
    switch (s) {
        case 0: return g_a2;
        case 1: return g_zb1;
        case 2: return g_zb2;
        case 3: return g_az;
        case 4: return g_w2;
        default: return g_w4;
    }
}

__device__ __forceinline__ float warpSum(float v) {
#pragma unroll
    for (int o = 16; o > 0; o >>= 1) v += __shfl_xor_sync(0xffffffffu, v, o);
    return v;
}
__device__ __forceinline__ float warpMax(float v) {
#pragma unroll
    for (int o = 16; o > 0; o >>= 1) v = fmaxf(v, __shfl_xor_sync(0xffffffffu, v, o));
    return v;
}

// ---------------- init: zero t1 accumulator + norm scalars ------------------
__global__ void init_kernel() {
    int i = blockIdx.x * 256 + threadIdx.x;
    if (i < NH * ML * DH) g_t1[i] = 0.0f;
    if (i == 0) { g_colmax = 0.0f; g_rowmax = 0.0f; }
}

// ---------------- layernorm: one block (128 thr) per row ---------------------
__global__ void layernorm_kernel(const float* __restrict__ x,
                                 const float* __restrict__ w,
                                 const float* __restrict__ b) {
    int row = blockIdx.x;
    int t = threadIdx.x;                       // 128 threads, 4 floats each
    const float4 v = ((const float4*)(x + (size_t)row * DIMX))[t];
    __shared__ float red[4];
    float s = v.x + v.y + v.z + v.w;
    s = warpSum(s);
    if ((t & 31) == 0) red[t >> 5] = s;
    __syncthreads();
    float mu = (red[0] + red[1] + red[2] + red[3]) * (1.0f / DIMX);
    __syncthreads();
    float dx = v.x - mu, dy = v.y - mu, dz = v.z - mu, dw = v.w - mu;
    float q = dx * dx + dy * dy + dz * dz + dw * dw;
    q = warpSum(q);
    if ((t & 31) == 0) red[t >> 5] = q;
    __syncthreads();
    float var = (red[0] + red[1] + red[2] + red[3]) * (1.0f / DIMX);
    float rstd = rsqrtf(var + 1e-5f);
    float4 wv = ((const float4*)w)[t];
    float4 bv = ((const float4*)b)[t];
    float4 o;
    o.x = dx * rstd * wv.x + bv.x;
    o.y = dy * rstd * wv.y + bv.y;
    o.z = dz * rstd * wv.z + bv.z;
    o.w = dw * rstd * wv.w + bv.w;
    ((float4*)(g_h + (size_t)row * DIMX))[t] = o;
}

// ---------------- SGEMM NT: C[m][n] = sum_k A[m][k]*B[n][k] (+bias+resid) ---
// 128x128 block tile, k-tile 8, 256 threads, 8x8 per thread.
// mode 0: A=g_h, C=g_qkv. mode 1: A=g_attnout, C=Cout.
__global__ void __launch_bounds__(256) sgemm_nt(int mode, const float* __restrict__ B,
                                                float* Cout, int M, int N, int K,
                                                const float* __restrict__ bias,
                                                const float* __restrict__ resid) {
    const float* A = (mode == 0) ? g_h : g_attnout;
    float* C = (mode == 0) ? g_qkv : Cout;

    __shared__ __align__(16) float As[8][128];
    __shared__ __align__(16) float Bs[8][128];
    int bm = blockIdx.y * 128, bn = blockIdx.x * 128;
    int tid = threadIdx.x;
    int lrow = tid >> 1, lk = (tid & 1) * 4;
    int tx = tid & 15, ty = tid >> 4;

    float acc[8][8];
#pragma unroll
    for (int i = 0; i < 8; i++)
#pragma unroll
        for (int j = 0; j < 8; j++) acc[i][j] = 0.0f;

    const float* Ap = A + (size_t)(bm + lrow) * K + lk;
    const float* Bp = B + (size_t)(bn + lrow) * K + lk;

    for (int k0 = 0; k0 < K; k0 += 8) {
        float4 av = *(const float4*)(Ap + k0);
        float4 bv = *(const float4*)(Bp + k0);
        __syncthreads();
        As[lk + 0][lrow] = av.x; As[lk + 1][lrow] = av.y;
        As[lk + 2][lrow] = av.z; As[lk + 3][lrow] = av.w;
        Bs[lk + 0][lrow] = bv.x; Bs[lk + 1][lrow] = bv.y;
        Bs[lk + 2][lrow] = bv.z; Bs[lk + 3][lrow] = bv.w;
        __syncthreads();
#pragma unroll
        for (int kk = 0; kk < 8; kk++) {
            float a[8], bfr[8];
            *(float4*)&a[0]   = *(const float4*)&As[kk][ty * 4];
            *(float4*)&a[4]   = *(const float4*)&As[kk][64 + ty * 4];
            *(float4*)&bfr[0] = *(const float4*)&Bs[kk][tx * 4];
            *(float4*)&bfr[4] = *(const float4*)&Bs[kk][64 + tx * 4];
#pragma unroll
            for (int i = 0; i < 8; i++)
#pragma unroll
                for (int j = 0; j < 8; j++) acc[i][j] += a[i] * bfr[j];
        }
    }

#pragma unroll
    for (int i = 0; i < 8; i++) {
        int m = bm + ((i < 4) ? (ty * 4 + i) : (64 + ty * 4 + i - 4));
#pragma unroll
        for (int g = 0; g < 2; g++) {
            int n = bn + g * 64 + tx * 4;
            float4 o;
            o.x = acc[i][g * 4 + 0];
            o.y = acc[i][g * 4 + 1];
            o.z = acc[i][g * 4 + 2];
            o.w = acc[i][g * 4 + 3];
            if (bias) {
                o.x += bias[n]; o.y += bias[n + 1]; o.z += bias[n + 2]; o.w += bias[n + 3];
            }
            if (resid) {
                float4 r = *(const float4*)(resid + (size_t)m * N + n);
                o.x += r.x; o.y += r.y; o.z += r.z; o.w += r.w;
            }
            *(float4*)(C + (size_t)m * N + n) = o;
        }
    }
}

// ---------------- landmark pooling (q scaled by DH^-0.5) --------------------
__global__ void pool_kernel() {
    int idx = blockIdx.x * 256 + threadIdx.x;   // 131072 = NH*ML*DH
    int d = idx & 63;
    int m = (idx >> 6) & 255;
    int h = idx >> 14;
    int qoff = h * DH + d;
    int koff = INNER + h * DH + d;
    const float* base = g_qkv + (size_t)(m * LP) * TIN;
    float sq = 0.0f, sk = 0.0f;
#pragma unroll 8
    for (int i = 0; i < LP; i++) {
        sq += base[(size_t)i * TIN + qoff];
        sk += base[(size_t)i * TIN + koff];
    }
    g_ql[idx] = sq * (0.125f / 64.0f);
    g_kl[idx] = sk * (1.0f / 64.0f);
}

// ---------------- attn2 = softmax(q_l k_l^T): block per (h, row) ------------
__global__ void attn2_kernel() {
    int i = blockIdx.x, h = blockIdx.y;
    int t = threadIdx.x;                       // 256 threads = 256 columns
    __shared__ float qrow[64];
    __shared__ float redm[8], reds[8];
    if (t < 64) qrow[t] = g_ql[((h * ML) + i) * DH + t];
    __syncthreads();
    const float4* kr = (const float4*)(g_kl + (size_t)((h * ML) + t) * DH);
    const float4* q4 = (const float4*)qrow;
    float dot = 0.0f;
#pragma unroll
    for (int l = 0; l < 16; l++) {
        float4 kv = kr[l], qv = q4[l];
        dot += kv.x * qv.x + kv.y * qv.y + kv.z * qv.z + kv.w * qv.w;
    }
    float mx = warpMax(dot);
    if ((t & 31) == 0) redm[t >> 5] = mx;
    __syncthreads();
    float bm = redm[0];
#pragma unroll
    for (int k = 1; k < 8; k++) bm = fmaxf(bm, redm[k]);
    float p = expf(dot - bm);
    float ws = warpSum(p);
    if ((t & 31) == 0) reds[t >> 5] = ws;
    __syncthreads();
    float bs = 0.0f;
#pragma unroll
    for (int k = 0; k < 8; k++) bs += reds[k];
    g_a2[((h * ML) + i) * ML + t] = p / bs;
}

// ---------------- pinv norm scalars ------------------------------------------
__global__ void rowsum_kernel() {   // max row-sum -> g_colmax
    int i = blockIdx.x, h = blockIdx.y, t = threadIdx.x;
    __shared__ float red[8];
    float v = fabsf(g_a2[((h * ML) + i) * ML + t]);
    v = warpSum(v);
    if ((t & 31) == 0) red[t >> 5] = v;
    __syncthreads();
    if (t == 0) {
        float s = 0.0f;
#pragma unroll
        for (int k = 0; k < 8; k++) s += red[k];
        atomicMax((int*)&g_colmax, __float_as_int(s));
    }
}
__global__ void colsum_kernel() {   // max col-sum -> g_rowmax
    int h = blockIdx.x, j = threadIdx.x;
    float s = 0.0f;
    for (int i = 0; i < ML; i++) s += fabsf(g_a2[((h * ML) + i) * ML + j]);
    atomicMax((int*)&g_rowmax, __float_as_int(s));
}
__global__ void tscale_kernel() {   // z0 = a^T / (col*row)
    int i = blockIdx.x, h = blockIdx.y, j = threadIdx.x;
    float inv = 1.0f / (g_colmax * g_rowmax);
    g_zb1[((h * ML) + i) * ML + j] = g_a2[((h * ML) + j) * ML + i] * inv;
}

// ---------------- 256^3 batched GEMM with epilogue C = a*A + b*(A@B) --------
__global__ void __launch_bounds__(256) gemm256_kernel(int cs, int as, int bs,
                                                      float alpha, float beta) {
    const float* A = pickbuf(as);
    const float* B = pickbuf(bs);
    float* C = pickbuf(cs);
    int h = blockIdx.y;
    int i0 = (blockIdx.x >> 2) * 64, j0 = (blockIdx.x & 3) * 64;
    size_t hb = (size_t)h * ML * ML;

    __shared__ __align__(16) float Ast[32][68];
    __shared__ __align__(16) float Bsm[32][68];
    int t = threadIdx.x;
    int tx = t & 15, ty = t >> 4;
    float acc[4][4];
#pragma unroll
    for (int i = 0; i < 4; i++)
#pragma unroll
        for (int j = 0; j < 4; j++) acc[i][j] = 0.0f;

    for (int k0 = 0; k0 < ML; k0 += 32) {
        __syncthreads();
#pragma unroll
        for (int l = 0; l < 2; l++) {
            int li = t + l * 256;             // 512 float4 of A (64 rows x 32 k)
            int row = li >> 3, k4 = li & 7;
            float4 v = *(const float4*)(A + hb + (size_t)(i0 + row) * ML + k0 + k4 * 4);
            Ast[k4 * 4 + 0][row] = v.x; Ast[k4 * 4 + 1][row] = v.y;
            Ast[k4 * 4 + 2][row] = v.z; Ast[k4 * 4 + 3][row] = v.w;
        }
#pragma unroll
        for (int l = 0; l < 2; l++) {
            int li = t + l * 256;             // 512 float4 of B (32 k x 64 cols)
            int kk = li >> 4, c4 = li & 15;
            *(float4*)&Bsm[kk][c4 * 4] =
                *(const float4*)(B + hb + (size_t)(k0 + kk) * ML + j0 + c4 * 4);
        }
        __syncthreads();
#pragma unroll
        for (int kk = 0; kk < 32; kk++) {
            float4 a4 = *(const float4*)&Ast[kk][ty * 4];
            float4 b4 = *(const float4*)&Bsm[kk][tx * 4];
            float a[4] = {a4.x, a4.y, a4.z, a4.w};
            float bb[4] = {b4.x, b4.y, b4.z, b4.w};
#pragma unroll
            for (int i = 0; i < 4; i++)
#pragma unroll
                for (int j = 0; j < 4; j++) acc[i][j] += a[i] * bb[j];
        }
    }
#pragma unroll
    for (int i = 0; i < 4; i++) {
        int gi = i0 + ty * 4 + i;
        float4 av = *(const float4*)(A + hb + (size_t)gi * ML + j0 + tx * 4);
        float4 o;
        o.x = alpha * av.x + beta * acc[i][0];
        o.y = alpha * av.y + beta * acc[i][1];
        o.z = alpha * av.z + beta * acc[i][2];
        o.w = alpha * av.w + beta * acc[i][3];
        *(float4*)(C + hb + (size_t)gi * ML + j0 + tx * 4) = o;
    }
}

// ---------------- attn3 logits: q_l @ k^T  -> g_attn3[h][m][n] --------------
__global__ void __launch_bounds__(256) attn3_kernel() {
    extern __shared__ float sm[];
    float* qls = sm;                 // 64*65
    float* ks  = sm + 64 * 65;       // 256*65
    int h = blockIdx.z, m0 = blockIdx.y * 64, n0 = blockIdx.x * 256;
    int t = threadIdx.x;
#pragma unroll
    for (int l = 0; l < 16; l++) {
        int li = t + l * 256;
        int r = li >> 6, kk = li & 63;
        qls[r * 65 + kk] = g_ql[((h * ML) + m0 + r) * DH + kk];
    }
    for (int l = 0; l < 64; l++) {
        int li = t + l * 256;
        int n = li >> 6, kk = li & 63;
        ks[n * 65 + kk] = g_qkv[(size_t)(n0 + n) * TIN + INNER + h * DH + kk];
    }
    __syncthreads();
    float kv[64];
    const float* myk = ks + t * 65;
#pragma unroll
    for (int kk = 0; kk < 64; kk++) kv[kk] = myk[kk];
    for (int r = 0; r < 64; r++) {
        const float* q = qls + r * 65;
        float dot = 0.0f;
#pragma unroll
        for (int kk = 0; kk < 64; kk++) dot += q[kk] * kv[kk];
        g_attn3[(size_t)((h * ML) + m0 + r) * NSEQ + n0 + t] = dot;
    }
}

// ---------------- softmax over 16384-length rows (attn3, in place) ----------
__global__ void __launch_bounds__(256) softmax16k_kernel() {
    int row = blockIdx.x;
    float* p = g_attn3 + (size_t)row * NSEQ;
    int t = threadIdx.x;
    __shared__ float red[8];
    float4 v[16];
    float mx = -1e30f;
#pragma unroll
    for (int l = 0; l < 16; l++) {
        v[l] = ((float4*)p)[t + l * 256];
        mx = fmaxf(mx, fmaxf(fmaxf(v[l].x, v[l].y), fmaxf(v[l].z, v[l].w)));
    }
    mx = warpMax(mx);
    if ((t & 31) == 0) red[t >> 5] = mx;
    __syncthreads();
    float bm = red[0];
#pragma unroll
    for (int k = 1; k < 8; k++) bm = fmaxf(bm, red[k]);
    float s = 0.0f;
#pragma unroll
    for (int l = 0; l < 16; l++) {
        v[l].x = expf(v[l].x - bm); v[l].y = expf(v[l].y - bm);
        v[l].z = expf(v[l].z - bm); v[l].w = expf(v[l].w - bm);
        s += v[l].x + v[l].y + v[l].z + v[l].w;
    }
    s = warpSum(s);
    __syncthreads();
    if ((t & 31) == 0) red[t >> 5] = s;
    __syncthreads();
    float bs = 0.0f;
#pragma unroll
    for (int k = 0; k < 8; k++) bs += red[k];
    float inv = 1.0f / bs;
#pragma unroll
    for (int l = 0; l < 16; l++) {
        v[l].x *= inv; v[l].y *= inv; v[l].z *= inv; v[l].w *= inv;
        ((float4*)p)[t + l * 256] = v[l];
    }
}

// ---------------- t1 = attn3 @ v (split-K, atomic accumulate) ---------------
__global__ void __launch_bounds__(256) pv_kernel() {
    int h = blockIdx.z, m0 = blockIdx.y * 32, kc = blockIdx.x;
    int t = threadIdx.x;
    __shared__ __align__(16) float As[32][33];
    __shared__ __align__(16) float Vs[32][65];
    int d = t & 63, rg = t >> 6;
    float acc[8];
#pragma unroll
    for (int i = 0; i < 8; i++) acc[i] = 0.0f;

    int kbase0 = kc * 512;
    for (int ks0 = 0; ks0 < 512; ks0 += 32) {
        int kb = kbase0 + ks0;
        __syncthreads();
        {
            int r = t >> 5, kk = t & 31;
#pragma unroll
            for (int l = 0; l < 4; l++)
                As[r + l * 8][kk] =
                    g_attn3[(size_t)((h * ML) + m0 + r + l * 8) * NSEQ + kb + kk];
        }
        {
            int kk = t >> 3, d0 = (t & 7) * 8;
            const float* vp = g_qkv + (size_t)(kb + kk) * TIN + 2 * INNER + h * DH + d0;
#pragma unroll
            for (int j = 0; j < 8; j++) Vs[kk][d0 + j] = vp[j];
        }
        __syncthreads();
#pragma unroll
        for (int kk = 0; kk < 32; kk++) {
            float vv = Vs[kk][d];
#pragma unroll
            for (int i = 0; i < 8; i++) acc[i] += As[rg * 8 + i][kk] * vv;
        }
    }
#pragma unroll
    for (int i = 0; i < 8; i++)
        atomicAdd(&g_t1[((h * ML) + m0 + rg * 8 + i) * DH + d], acc[i]);
}

// ---------------- t2 = pinv(attn2) @ t1 --------------------------------------
__global__ void t2_kernel(int zsel) {
    const float* Z = pickbuf(zsel);
    int idx = blockIdx.x * 256 + threadIdx.x;   // 131072
    int d = idx & 63, m = (idx >> 6) & 255, h = idx >> 14;
    const float* zr = Z + ((size_t)(h * ML) + m) * ML;
    float c = 0.0f;
#pragma unroll 4
    for (int k = 0; k < ML; k++) c += zr[k] * g_t1[((h * ML) + k) * DH + d];
    g_t2[idx] = c;
}

// ---------------- fused: out = softmax(q k_l^T) @ t2, 64 rows/block ----------
// smem: kls 256x65 + t2s 256x65 + qs 64x65 + lg 64x256 = 215296 B
__global__ void __launch_bounds__(256) fused_out_kernel() {
    extern __shared__ float sm[];
    float* kls = sm;                        // 16640
    float* t2s = sm + 16640;                // 16640
    float* qs  = sm + 33280;                // 4160
    float* lg  = sm + 37440;                // 16384
    int h = blockIdx.y, n0 = blockIdx.x * 64;
    int t = threadIdx.x;

#pragma unroll
    for (int l = 0; l < 64; l++) {
        int li = t + l * 256;
        int m = li >> 6, kk = li & 63;
        kls[m * 65 + kk] = g_kl[(size_t)h * ML * DH + li];
        t2s[m * 65 + kk] = g_t2[(size_t)h * ML * DH + li];
    }
#pragma unroll
    for (int l = 0; l < 16; l++) {
        int li = t + l * 256;
        int r = li >> 6, kk = li & 63;
        qs[r * 65 + kk] = g_qkv[(size_t)(n0 + r) * TIN + h * DH + kk] * 0.125f;
    }
    __syncthreads();

    {   // logits: thread t owns landmark column m=t
        float kv[64];
        const float* myk = kls + t * 65;
#pragma unroll
        for (int kk = 0; kk < 64; kk++) kv[kk] = myk[kk];
        for (int r = 0; r < 64; r++) {
            const float* q = qs + r * 65;
            float dot = 0.0f;
#pragma unroll
            for (int kk = 0; kk < 64; kk++) dot += q[kk] * kv[kk];
            lg[r * 256 + t] = dot;
        }
    }
    __syncthreads();

    {   // softmax: warp w handles rows w*8 .. w*8+7
        int w = t >> 5, lane = t & 31;
        for (int r = w * 8; r < w * 8 + 8; r++) {
            float* row = lg + r * 256;
            float vals[8];
            float mx = -1e30f;
#pragma unroll
            for (int i = 0; i < 8; i++) { vals[i] = row[lane + i * 32]; mx = fmaxf(mx, vals[i]); }
            mx = warpMax(mx);
            float s = 0.0f;
#pragma unroll
            for (int i = 0; i < 8; i++) { vals[i] = expf(vals[i] - mx); s += vals[i]; }
            s = warpSum(s);
            float inv = 1.0f / s;
#pragma unroll
            for (int i = 0; i < 8; i++) row[lane + i * 32] = vals[i] * inv;
        }
    }
    __syncthreads();

    {   // out[r][d] = sum_m p[r][m] * t2[m][d]; thread: d = t&63, 16 rows
        int d = t & 63, rg = t >> 6;
        float acc[16];
#pragma unroll
        for (int i = 0; i < 16; i++) acc[i] = 0.0f;
        for (int m = 0; m < ML; m += 4) {
            float c0 = t2s[(m + 0) * 65 + d];
            float c1 = t2s[(m + 1) * 65 + d];
            float c2 = t2s[(m + 2) * 65 + d];
            float c3 = t2s[(m + 3) * 65 + d];
#pragma unroll
            for (int i = 0; i < 16; i++) {
                float4 p4 = *(const float4*)&lg[(rg * 16 + i) * 256 + m];
                acc[i] += p4.x * c0 + p4.y * c1 + p4.z * c2 + p4.w * c3;
            }
        }
#pragma unroll
        for (int i = 0; i < 16; i++)
            g_attnout[(size_t)(n0 + rg * 16 + i) * INNER + h * DH + d] = acc[i];
    }
}

// ---------------- residual depthwise conv add --------------------------------
__global__ void conv_add_kernel(const float* __restrict__ cw) {
    int h = blockIdx.y;
    int t = threadIdx.x;
    int n = blockIdx.x * 4 + (t >> 6);
    int d = t & 63;
    __shared__ float w[KSZ];
    if (t < KSZ) w[t] = cw[h * KSZ + t];
    __syncthreads();
    size_t voff = (size_t)2 * INNER + h * DH + d;
    float acc = 0.0f;
#pragma unroll
    for (int j = 0; j < KSZ; j++) {
        int nn = n + j - 16;
        if (nn >= 0 && nn < NSEQ) acc += w[j] * g_qkv[(size_t)nn * TIN + voff];
    }
    g_attnout[(size_t)n * INNER + h * DH + d] += acc;
}

// ---------------- launch ------------------------------------------------------
extern "C" void kernel_launch(void* const* d_in, const int* in_sizes, int n_in,
                              void* d_out, int out_size) {
    const float* x    = (const float*)d_in[0];
    const float* nw   = (const float*)d_in[1];
    const float* nb   = (const float*)d_in[2];
    const float* wqkv = (const float*)d_in[3];
    const float* wout = (const float*)d_in[4];
    const float* bout = (const float*)d_in[5];
    const float* cw   = (const float*)d_in[6];
    float* out = (float*)d_out;

    cudaFuncSetAttribute(attn3_kernel, cudaFuncAttributeMaxDynamicSharedMemorySize, 83200);
    cudaFuncSetAttribute(fused_out_kernel, cudaFuncAttributeMaxDynamicSharedMemorySize, 215296);

    init_kernel<<<512, 256>>>();
    layernorm_kernel<<<NSEQ, 128>>>(x, nw, nb);

    // qkv = h @ w_qkv^T  (M=16384, N=1536, K=512)
    sgemm_nt<<<dim3(12, 128), 256>>>(0, wqkv, nullptr, NSEQ, TIN, DIMX, nullptr, nullptr);

    pool_kernel<<<512, 256>>>();
    attn2_kernel<<<dim3(ML, NH), 256>>>();
    rowsum_kernel<<<dim3(ML, NH), 256>>>();
    colsum_kernel<<<NH, 256>>>();
    tscale_kernel<<<dim3(ML, NH), 256>>>();

    // Moore-Penrose iterations: z' = 3.25 Z - 0.25 Z (15AZ - AZ(7AZ - AZ^2)...)
    // buffers: 0=a2 1=zb1 2=zb2 3=az 4=w2 5=w4
    int zi = 1, zo = 2;
    for (int it = 0; it < 6; it++) {
        gemm256_kernel<<<dim3(16, NH), 256>>>(3, 0, zi, 0.0f, 1.0f);        // AZ = a@z
        gemm256_kernel<<<dim3(16, NH), 256>>>(4, 3, 3, 7.0f, -1.0f);        // W2 = 7AZ - AZ*AZ
        gemm256_kernel<<<dim3(16, NH), 256>>>(5, 3, 4, 15.0f, -1.0f);       // W4 = 15AZ - AZ*W2
        gemm256_kernel<<<dim3(16, NH), 256>>>(zo, zi, 5, 3.25f, -0.25f);    // Z' = 3.25Z - .25 Z*W4
        int tmp = zi; zi = zo; zo = tmp;
    }

    attn3_kernel<<<dim3(64, 4, NH), 256, 83200>>>();
    softmax16k_kernel<<<NH * ML, 256>>>();
    pv_kernel<<<dim3(32, 8, NH), 256>>>();
    t2_kernel<<<512, 256>>>(zi);

    fused_out_kernel<<<dim3(NSEQ / 64, NH), 256, 215296>>>();
    conv_add_kernel<<<dim3(NSEQ / 4, NH), 256>>>(cw);

    // out = attnout @ w_out^T + b_out + x  (M=16384, N=512, K=512)
    sgemm_nt<<<dim3(4, 128), 256>>>(1, wout, out, NSEQ, DIMX, INNER, bout, x);
}

// round 15
// speedup vs baseline: 1.0026x; 1.0026x over previous
#include <cuda_runtime.h>

#define NSEQ  16384
#define DIMX  512
#define NH    8
#define DH    64
#define INNER 512
#define ML    256
#define LP    64
#define KSZ   33
#define TIN   1536

// ---------------- scratch (device globals; no allocations allowed) ----------
__device__ float g_h[NSEQ * DIMX];
__device__ float g_qkv[NSEQ * TIN];
__device__ float g_ql[NH * ML * DH];
__device__ float g_kl[NH * ML * DH];
__device__ float g_a2[NH * ML * ML];
__device__ float g_zb1[NH * ML * ML];
__device__ float g_zb2[NH * ML * ML];
__device__ float g_az[NH * ML * ML];
__device__ float g_w2[NH * ML * ML];
__device__ float g_w4[NH * ML * ML];
__device__ float g_attn3[NH * ML * NSEQ];   // 134 MB
__device__ float g_t1[NH * ML * DH];
__device__ float g_t2[NH * ML * DH];
__device__ float g_attnout[NSEQ * INNER];
__device__ float g_colmax;
__device__ float g_rowmax;

__device__ __forceinline__ float* pickbuf(int s) {
    switch (s) {
        case 0: return g_a2;
        case 1: return g_zb1;
        case 2: return g_zb2;
        case 3: return g_az;
        case 4: return g_w2;
        default: return g_w4;
    }
}

__device__ __forceinline__ float warpSum(float v) {
#pragma unroll
    for (int o = 16; o > 0; o >>= 1) v += __shfl_xor_sync(0xffffffffu, v, o);
    return v;
}
__device__ __forceinline__ float warpMax(float v) {
#pragma unroll
    for (int o = 16; o > 0; o >>= 1) v = fmaxf(v, __shfl_xor_sync(0xffffffffu, v, o));
    return v;
}

// ---------------- init: zero t1 accumulator + norm scalars ------------------
__global__ void init_kernel() {
    int i = blockIdx.x * 256 + threadIdx.x;
    if (i < NH * ML * DH) g_t1[i] = 0.0f;
    if (i == 0) { g_colmax = 0.0f; g_rowmax = 0.0f; }
}

// ---------------- layernorm: one block (128 thr) per row ---------------------
__global__ void layernorm_kernel(const float* __restrict__ x,
                                 const float* __restrict__ w,
                                 const float* __restrict__ b) {
    int row = blockIdx.x;
    int t = threadIdx.x;                       // 128 threads, 4 floats each
    const float4 v = ((const float4*)(x + (size_t)row * DIMX))[t];
    __shared__ float red[4];
    float s = v.x + v.y + v.z + v.w;
    s = warpSum(s);
    if ((t & 31) == 0) red[t >> 5] = s;
    __syncthreads();
    float mu = (red[0] + red[1] + red[2] + red[3]) * (1.0f / DIMX);
    __syncthreads();
    float dx = v.x - mu, dy = v.y - mu, dz = v.z - mu, dw = v.w - mu;
    float q = dx * dx + dy * dy + dz * dz + dw * dw;
    q = warpSum(q);
    if ((t & 31) == 0) red[t >> 5] = q;
    __syncthreads();
    float var = (red[0] + red[1] + red[2] + red[3]) * (1.0f / DIMX);
    float rstd = rsqrtf(var + 1e-5f);
    float4 wv = ((const float4*)w)[t];
    float4 bv = ((const float4*)b)[t];
    float4 o;
    o.x = dx * rstd * wv.x + bv.x;
    o.y = dy * rstd * wv.y + bv.y;
    o.z = dz * rstd * wv.z + bv.z;
    o.w = dw * rstd * wv.w + bv.w;
    ((float4*)(g_h + (size_t)row * DIMX))[t] = o;
}

// ---------------- SGEMM NT: C[m][n] = sum_k A[m][k]*B[n][k] (+bias+resid) ---
// 128x128 block tile, k-tile 8, 256 threads, 8x8 per thread.
// mode 0: A=g_h, C=g_qkv. mode 1: A=g_attnout, C=Cout.
__global__ void __launch_bounds__(256) sgemm_nt(int mode, const float* __restrict__ B,
                                                float* Cout, int M, int N, int K,
                                                const float* __restrict__ bias,
                                                const float* __restrict__ resid) {
    const float* A = (mode == 0) ? g_h : g_attnout;
    float* C = (mode == 0) ? g_qkv : Cout;

    __shared__ __align__(16) float As[8][128];
    __shared__ __align__(16) float Bs[8][128];
    int bm = blockIdx.y * 128, bn = blockIdx.x * 128;
    int tid = threadIdx.x;
    int lrow = tid >> 1, lk = (tid & 1) * 4;
    int tx = tid & 15, ty = tid >> 4;

    float acc[8][8];
#pragma unroll
    for (int i = 0; i < 8; i++)
#pragma unroll
        for (int j = 0; j < 8; j++) acc[i][j] = 0.0f;

    const float* Ap = A + (size_t)(bm + lrow) * K + lk;
    const float* Bp = B + (size_t)(bn + lrow) * K + lk;

    for (int k0 = 0; k0 < K; k0 += 8) {
        float4 av = *(const float4*)(Ap + k0);
        float4 bv = *(const float4*)(Bp + k0);
        __syncthreads();
        As[lk + 0][lrow] = av.x; As[lk + 1][lrow] = av.y;
        As[lk + 2][lrow] = av.z; As[lk + 3][lrow] = av.w;
        Bs[lk + 0][lrow] = bv.x; Bs[lk + 1][lrow] = bv.y;
        Bs[lk + 2][lrow] = bv.z; Bs[lk + 3][lrow] = bv.w;
        __syncthreads();
#pragma unroll
        for (int kk = 0; kk < 8; kk++) {
            float a[8], bfr[8];
            *(float4*)&a[0]   = *(const float4*)&As[kk][ty * 4];
            *(float4*)&a[4]   = *(const float4*)&As[kk][64 + ty * 4];
            *(float4*)&bfr[0] = *(const float4*)&Bs[kk][tx * 4];
            *(float4*)&bfr[4] = *(const float4*)&Bs[kk][64 + tx * 4];
#pragma unroll
            for (int i = 0; i < 8; i++)
#pragma unroll
                for (int j = 0; j < 8; j++) acc[i][j] += a[i] * bfr[j];
        }
    }

#pragma unroll
    for (int i = 0; i < 8; i++) {
        int m = bm + ((i < 4) ? (ty * 4 + i) : (64 + ty * 4 + i - 4));
#pragma unroll
        for (int g = 0; g < 2; g++) {
            int n = bn + g * 64 + tx * 4;
            float4 o;
            o.x = acc[i][g * 4 + 0];
            o.y = acc[i][g * 4 + 1];
            o.z = acc[i][g * 4 + 2];
            o.w = acc[i][g * 4 + 3];
            if (bias) {
                o.x += bias[n]; o.y += bias[n + 1]; o.z += bias[n + 2]; o.w += bias[n + 3];
            }
            if (resid) {
                float4 r = *(const float4*)(resid + (size_t)m * N + n);
                o.x += r.x; o.y += r.y; o.z += r.z; o.w += r.w;
            }
            *(float4*)(C + (size_t)m * N + n) = o;
        }
    }
}

// ---------------- landmark pooling (q scaled by DH^-0.5) --------------------
__global__ void pool_kernel() {
    int idx = blockIdx.x * 256 + threadIdx.x;   // 131072 = NH*ML*DH
    int d = idx & 63;
    int m = (idx >> 6) & 255;
    int h = idx >> 14;
    int qoff = h * DH + d;
    int koff = INNER + h * DH + d;
    const float* base = g_qkv + (size_t)(m * LP) * TIN;
    float sq = 0.0f, sk = 0.0f;
#pragma unroll 8
    for (int i = 0; i < LP; i++) {
        sq += base[(size_t)i * TIN + qoff];
        sk += base[(size_t)i * TIN + koff];
    }
    g_ql[idx] = sq * (0.125f / 64.0f);
    g_kl[idx] = sk * (1.0f / 64.0f);
}

// ---------------- attn2 = softmax(q_l k_l^T): block per (h, row) ------------
__global__ void attn2_kernel() {
    int i = blockIdx.x, h = blockIdx.y;
    int t = threadIdx.x;                       // 256 threads = 256 columns
    __shared__ float qrow[64];
    __shared__ float redm[8], reds[8];
    if (t < 64) qrow[t] = g_ql[((h * ML) + i) * DH + t];
    __syncthreads();
    const float4* kr = (const float4*)(g_kl + (size_t)((h * ML) + t) * DH);
    const float4* q4 = (const float4*)qrow;
    float dot = 0.0f;
#pragma unroll
    for (int l = 0; l < 16; l++) {
        float4 kv = kr[l], qv = q4[l];
        dot += kv.x * qv.x + kv.y * qv.y + kv.z * qv.z + kv.w * qv.w;
    }
    float mx = warpMax(dot);
    if ((t & 31) == 0) redm[t >> 5] = mx;
    __syncthreads();
    float bm = redm[0];
#pragma unroll
    for (int k = 1; k < 8; k++) bm = fmaxf(bm, redm[k]);
    float p = expf(dot - bm);
    float ws = warpSum(p);
    if ((t & 31) == 0) reds[t >> 5] = ws;
    __syncthreads();
    float bs = 0.0f;
#pragma unroll
    for (int k = 0; k < 8; k++) bs += reds[k];
    g_a2[((h * ML) + i) * ML + t] = p / bs;
}

// ---------------- pinv norm scalars ------------------------------------------
__global__ void rowsum_kernel() {   // max row-sum -> g_colmax
    int i = blockIdx.x, h = blockIdx.y, t = threadIdx.x;
    __shared__ float red[8];
    float v = fabsf(g_a2[((h * ML) + i) * ML + t]);
    v = warpSum(v);
    if ((t & 31) == 0) red[t >> 5] = v;
    __syncthreads();
    if (t == 0) {
        float s = 0.0f;
#pragma unroll
        for (int k = 0; k < 8; k++) s += red[k];
        atomicMax((int*)&g_colmax, __float_as_int(s));
    }
}
__global__ void colsum_kernel() {   // max col-sum -> g_rowmax
    int h = blockIdx.x, j = threadIdx.x;
    float s = 0.0f;
    for (int i = 0; i < ML; i++) s += fabsf(g_a2[((h * ML) + i) * ML + j]);
    atomicMax((int*)&g_rowmax, __float_as_int(s));
}
__global__ void tscale_kernel() {   // z0 = a^T / (col*row)
    int i = blockIdx.x, h = blockIdx.y, j = threadIdx.x;
    float inv = 1.0f / (g_colmax * g_rowmax);
    g_zb1[((h * ML) + i) * ML + j] = g_a2[((h * ML) + j) * ML + i] * inv;
}

// ---------------- 256^3 batched GEMM with epilogue C = a*A + b*(A@B) --------
__global__ void __launch_bounds__(256) gemm256_kernel(int cs, int as, int bs,
                                                      float alpha, float beta) {
    const float* A = pickbuf(as);
    const float* B = pickbuf(bs);
    float* C = pickbuf(cs);
    int h = blockIdx.y;
    int i0 = (blockIdx.x >> 2) * 64, j0 = (blockIdx.x & 3) * 64;
    size_t hb = (size_t)h * ML * ML;

    __shared__ __align__(16) float Ast[32][68];
    __shared__ __align__(16) float Bsm[32][68];
    int t = threadIdx.x;
    int tx = t & 15, ty = t >> 4;
    float acc[4][4];
#pragma unroll
    for (int i = 0; i < 4; i++)
#pragma unroll
        for (int j = 0; j < 4; j++) acc[i][j] = 0.0f;

    for (int k0 = 0; k0 < ML; k0 += 32) {
        __syncthreads();
#pragma unroll
        for (int l = 0; l < 2; l++) {
            int li = t + l * 256;             // 512 float4 of A (64 rows x 32 k)
            int row = li >> 3, k4 = li & 7;
            float4 v = *(const float4*)(A + hb + (size_t)(i0 + row) * ML + k0 + k4 * 4);
            Ast[k4 * 4 + 0][row] = v.x; Ast[k4 * 4 + 1][row] = v.y;
            Ast[k4 * 4 + 2][row] = v.z; Ast[k4 * 4 + 3][row] = v.w;
        }
#pragma unroll
        for (int l = 0; l < 2; l++) {
            int li = t + l * 256;             // 512 float4 of B (32 k x 64 cols)
            int kk = li >> 4, c4 = li & 15;
            *(float4*)&Bsm[kk][c4 * 4] =
                *(const float4*)(B + hb + (size_t)(k0 + kk) * ML + j0 + c4 * 4);
        }
        __syncthreads();
#pragma unroll
        for (int kk = 0; kk < 32; kk++) {
            float4 a4 = *(const float4*)&Ast[kk][ty * 4];
            float4 b4 = *(const float4*)&Bsm[kk][tx * 4];
            float a[4] = {a4.x, a4.y, a4.z, a4.w};
            float bb[4] = {b4.x, b4.y, b4.z, b4.w};
#pragma unroll
            for (int i = 0; i < 4; i++)
#pragma unroll
                for (int j = 0; j < 4; j++) acc[i][j] += a[i] * bb[j];
        }
    }
#pragma unroll
    for (int i = 0; i < 4; i++) {
        int gi = i0 + ty * 4 + i;
        float4 av = *(const float4*)(A + hb + (size_t)gi * ML + j0 + tx * 4);
        float4 o;
        o.x = alpha * av.x + beta * acc[i][0];
        o.y = alpha * av.y + beta * acc[i][1];
        o.z = alpha * av.z + beta * acc[i][2];
        o.w = alpha * av.w + beta * acc[i][3];
        *(float4*)(C + hb + (size_t)gi * ML + j0 + tx * 4) = o;
    }
}

// ---------------- attn3 logits: q_l @ k^T  -> g_attn3[h][m][n] --------------
__global__ void __launch_bounds__(256) attn3_kernel() {
    extern __shared__ float sm[];
    float* qls = sm;                 // 64*65
    float* ks  = sm + 64 * 65;       // 256*65
    int h = blockIdx.z, m0 = blockIdx.y * 64, n0 = blockIdx.x * 256;
    int t = threadIdx.x;
#pragma unroll
    for (int l = 0; l < 16; l++) {
        int li = t + l * 256;
        int r = li >> 6, kk = li & 63;
        qls[r * 65 + kk] = g_ql[((h * ML) + m0 + r) * DH + kk];
    }
    for (int l = 0; l < 64; l++) {
        int li = t + l * 256;
        int n = li >> 6, kk = li & 63;
        ks[n * 65 + kk] = g_qkv[(size_t)(n0 + n) * TIN + INNER + h * DH + kk];
    }
    __syncthreads();
    float kv[64];
    const float* myk = ks + t * 65;
#pragma unroll
    for (int kk = 0; kk < 64; kk++) kv[kk] = myk[kk];
    for (int r = 0; r < 64; r++) {
        const float* q = qls + r * 65;
        float dot = 0.0f;
#pragma unroll
        for (int kk = 0; kk < 64; kk++) dot += q[kk] * kv[kk];
        g_attn3[(size_t)((h * ML) + m0 + r) * NSEQ + n0 + t] = dot;
    }
}

// ---------------- softmax over 16384-length rows (attn3, in place) ----------
__global__ void __launch_bounds__(256) softmax16k_kernel() {
    int row = blockIdx.x;
    float* p = g_attn3 + (size_t)row * NSEQ;
    int t = threadIdx.x;
    __shared__ float red[8];
    float4 v[16];
    float mx = -1e30f;
#pragma unroll
    for (int l = 0; l < 16; l++) {
        v[l] = ((float4*)p)[t + l * 256];
        mx = fmaxf(mx, fmaxf(fmaxf(v[l].x, v[l].y), fmaxf(v[l].z, v[l].w)));
    }
    mx = warpMax(mx);
    if ((t & 31) == 0) red[t >> 5] = mx;
    __syncthreads();
    float bm = red[0];
#pragma unroll
    for (int k = 1; k < 8; k++) bm = fmaxf(bm, red[k]);
    float s = 0.0f;
#pragma unroll
    for (int l = 0; l < 16; l++) {
        v[l].x = expf(v[l].x - bm); v[l].y = expf(v[l].y - bm);
        v[l].z = expf(v[l].z - bm); v[l].w = expf(v[l].w - bm);
        s += v[l].x + v[l].y + v[l].z + v[l].w;
    }
    s = warpSum(s);
    __syncthreads();
    if ((t & 31) == 0) red[t >> 5] = s;
    __syncthreads();
    float bs = 0.0f;
#pragma unroll
    for (int k = 0; k < 8; k++) bs += red[k];
    float inv = 1.0f / bs;
#pragma unroll
    for (int l = 0; l < 16; l++) {
        v[l].x *= inv; v[l].y *= inv; v[l].z *= inv; v[l].w *= inv;
        ((float4*)p)[t + l * 256] = v[l];
    }
}

// ---------------- t1 = attn3 @ v (split-K, atomic accumulate) ---------------
__global__ void __launch_bounds__(256) pv_kernel() {
    int h = blockIdx.z, m0 = blockIdx.y * 32, kc = blockIdx.x;
    int t = threadIdx.x;
    __shared__ __align__(16) float As[32][33];
    __shared__ __align__(16) float Vs[32][65];
    int d = t & 63, rg = t >> 6;
    float acc[8];
#pragma unroll
    for (int i = 0; i < 8; i++) acc[i] = 0.0f;

    int kbase0 = kc * 512;
    for (int ks0 = 0; ks0 < 512; ks0 += 32) {
        int kb = kbase0 + ks0;
        __syncthreads();
        {
            int r = t >> 5, kk = t & 31;
#pragma unroll
            for (int l = 0; l < 4; l++)
                As[r + l * 8][kk] =
                    g_attn3[(size_t)((h * ML) + m0 + r + l * 8) * NSEQ + kb + kk];
        }
        {
            int kk = t >> 3, d0 = (t & 7) * 8;
            const float* vp = g_qkv + (size_t)(kb + kk) * TIN + 2 * INNER + h * DH + d0;
#pragma unroll
            for (int j = 0; j < 8; j++) Vs[kk][d0 + j] = vp[j];
        }
        __syncthreads();
#pragma unroll
        for (int kk = 0; kk < 32; kk++) {
            float vv = Vs[kk][d];
#pragma unroll
            for (int i = 0; i < 8; i++) acc[i] += As[rg * 8 + i][kk] * vv;
        }
    }
#pragma unroll
    for (int i = 0; i < 8; i++)
        atomicAdd(&g_t1[((h * ML) + m0 + rg * 8 + i) * DH + d], acc[i]);
}

// ---------------- t2 = pinv(attn2) @ t1 --------------------------------------
__global__ void t2_kernel(int zsel) {
    const float* Z = pickbuf(zsel);
    int idx = blockIdx.x * 256 + threadIdx.x;   // 131072
    int d = idx & 63, m = (idx >> 6) & 255, h = idx >> 14;
    const float* zr = Z + ((size_t)(h * ML) + m) * ML;
    float c = 0.0f;
#pragma unroll 4
    for (int k = 0; k < ML; k++) c += zr[k] * g_t1[((h * ML) + k) * DH + d];
    g_t2[idx] = c;
}

// ---------------- fused: out = softmax(q k_l^T) @ t2, 64 rows/block ----------
// smem: kls 256x65 + t2s 256x65 + qs 64x65 + lg 64x256 = 215296 B
__global__ void __launch_bounds__(256) fused_out_kernel() {
    extern __shared__ float sm[];
    float* kls = sm;                        // 16640
    float* t2s = sm + 16640;                // 16640
    float* qs  = sm + 33280;                // 4160
    float* lg  = sm + 37440;                // 16384
    int h = blockIdx.y, n0 = blockIdx.x * 64;
    int t = threadIdx.x;

#pragma unroll
    for (int l = 0; l < 64; l++) {
        int li = t + l * 256;
        int m = li >> 6, kk = li & 63;
        kls[m * 65 + kk] = g_kl[(size_t)h * ML * DH + li];
        t2s[m * 65 + kk] = g_t2[(size_t)h * ML * DH + li];
    }
#pragma unroll
    for (int l = 0; l < 16; l++) {
        int li = t + l * 256;
        int r = li >> 6, kk = li & 63;
        qs[r * 65 + kk] = g_qkv[(size_t)(n0 + r) * TIN + h * DH + kk] * 0.125f;
    }
    __syncthreads();

    {   // logits: thread t owns landmark column m=t
        float kv[64];
        const float* myk = kls + t * 65;
#pragma unroll
        for (int kk = 0; kk < 64; kk++) kv[kk] = myk[kk];
        for (int r = 0; r < 64; r++) {
            const float* q = qs + r * 65;
            float dot = 0.0f;
#pragma unroll
            for (int kk = 0; kk < 64; kk++) dot += q[kk] * kv[kk];
            lg[r * 256 + t] = dot;
        }
    }
    __syncthreads();

    {   // softmax: warp w handles rows w*8 .. w*8+7
        int w = t >> 5, lane = t & 31;
        for (int r = w * 8; r < w * 8 + 8; r++) {
            float* row = lg + r * 256;
            float vals[8];
            float mx = -1e30f;
#pragma unroll
            for (int i = 0; i < 8; i++) { vals[i] = row[lane + i * 32]; mx = fmaxf(mx, vals[i]); }
            mx = warpMax(mx);
            float s = 0.0f;
#pragma unroll
            for (int i = 0; i < 8; i++) { vals[i] = expf(vals[i] - mx); s += vals[i]; }
            s = warpSum(s);
            float inv = 1.0f / s;
#pragma unroll
            for (int i = 0; i < 8; i++) row[lane + i * 32] = vals[i] * inv;
        }
    }
    __syncthreads();

    {   // out[r][d] = sum_m p[r][m] * t2[m][d]; thread: d = t&63, 16 rows
        int d = t & 63, rg = t >> 6;
        float acc[16];
#pragma unroll
        for (int i = 0; i < 16; i++) acc[i] = 0.0f;
        for (int m = 0; m < ML; m += 4) {
            float c0 = t2s[(m + 0) * 65 + d];
            float c1 = t2s[(m + 1) * 65 + d];
            float c2 = t2s[(m + 2) * 65 + d];
            float c3 = t2s[(m + 3) * 65 + d];
#pragma unroll
            for (int i = 0; i < 16; i++) {
                float4 p4 = *(const float4*)&lg[(rg * 16 + i) * 256 + m];
                acc[i] += p4.x * c0 + p4.y * c1 + p4.z * c2 + p4.w * c3;
            }
        }
#pragma unroll
        for (int i = 0; i < 16; i++)
            g_attnout[(size_t)(n0 + rg * 16 + i) * INNER + h * DH + d] = acc[i];
    }
}

// ---------------- residual depthwise conv add --------------------------------
__global__ void conv_add_kernel(const float* __restrict__ cw) {
    int h = blockIdx.y;
    int t = threadIdx.x;
    int n = blockIdx.x * 4 + (t >> 6);
    int d = t & 63;
    __shared__ float w[KSZ];
    if (t < KSZ) w[t] = cw[h * KSZ + t];
    __syncthreads();
    size_t voff = (size_t)2 * INNER + h * DH + d;
    float acc = 0.0f;
#pragma unroll
    for (int j = 0; j < KSZ; j++) {
        int nn = n + j - 16;
        if (nn >= 0 && nn < NSEQ) acc += w[j] * g_qkv[(size_t)nn * TIN + voff];
    }
    g_attnout[(size_t)n * INNER + h * DH + d] += acc;
}

// ---------------- launch ------------------------------------------------------
extern "C" void kernel_launch(void* const* d_in, const int* in_sizes, int n_in,
                              void* d_out, int out_size) {
    const float* x    = (const float*)d_in[0];
    const float* nw   = (const float*)d_in[1];
    const float* nb   = (const float*)d_in[2];
    const float* wqkv = (const float*)d_in[3];
    const float* wout = (const float*)d_in[4];
    const float* bout = (const float*)d_in[5];
    const float* cw   = (const float*)d_in[6];
    float* out = (float*)d_out;

    cudaFuncSetAttribute(attn3_kernel, cudaFuncAttributeMaxDynamicSharedMemorySize, 83200);
    cudaFuncSetAttribute(fused_out_kernel, cudaFuncAttributeMaxDynamicSharedMemorySize, 215296);

    init_kernel<<<512, 256>>>();
    layernorm_kernel<<<NSEQ, 128>>>(x, nw, nb);

    // qkv = h @ w_qkv^T  (M=16384, N=1536, K=512)
    sgemm_nt<<<dim3(12, 128), 256>>>(0, wqkv, nullptr, NSEQ, TIN, DIMX, nullptr, nullptr);

    pool_kernel<<<512, 256>>>();
    attn2_kernel<<<dim3(ML, NH), 256>>>();
    rowsum_kernel<<<dim3(ML, NH), 256>>>();
    colsum_kernel<<<NH, 256>>>();
    tscale_kernel<<<dim3(ML, NH), 256>>>();

    // Moore-Penrose iterations: z' = 3.25 Z - 0.25 Z (15AZ - AZ(7AZ - AZ^2)...)
    // buffers: 0=a2 1=zb1 2=zb2 3=az 4=w2 5=w4
    int zi = 1, zo = 2;
    for (int it = 0; it < 6; it++) {
        gemm256_kernel<<<dim3(16, NH), 256>>>(3, 0, zi, 0.0f, 1.0f);        // AZ = a@z
        gemm256_kernel<<<dim3(16, NH), 256>>>(4, 3, 3, 7.0f, -1.0f);        // W2 = 7AZ - AZ*AZ
        gemm256_kernel<<<dim3(16, NH), 256>>>(5, 3, 4, 15.0f, -1.0f);       // W4 = 15AZ - AZ*W2
        gemm256_kernel<<<dim3(16, NH), 256>>>(zo, zi, 5, 3.25f, -0.25f);    // Z' = 3.25Z - .25 Z*W4
        int tmp = zi; zi = zo; zo = tmp;
    }

    attn3_kernel<<<dim3(64, 4, NH), 256, 83200>>>();
    softmax16k_kernel<<<NH * ML, 256>>>();
    pv_kernel<<<dim3(32, 8, NH), 256>>>();
    t2_kernel<<<512, 256>>>(zi);

    fused_out_kernel<<<dim3(NSEQ / 64, NH), 256, 215296>>>();
    conv_add_kernel<<<dim3(NSEQ / 4, NH), 256>>>(cw);

    // out = attnout @ w_out^T + b_out + x  (M=16384, N=512, K=512)
    sgemm_nt<<<dim3(4, 128), 256>>>(1, wout, out, NSEQ, DIMX, INNER, bout, x);
}